// round 6
// baseline (speedup 1.0000x reference)
#include <cuda_runtime.h>
#include <cuda_bf16.h>
#include <math.h>
#include <stdint.h>

// ---------------- problem constants ----------------
#define CKD 64
#define QD 1620          // H*W
#define MD 32400
#define TOPK 20
#define CHD 1536         // OD*CVD

// ---------------- K1 tiling ----------------
#define QT 128           // q per block
#define MTILE 64         // m per iteration
#define NQB 13           // 13*128 = 1664 >= 1620
#define NCHUNK 22
#define CHUNKP 1536      // m per chunk (24 tiles of 64)
#define MPAD (NCHUNK * CHUNKP)   // 33792
#define CPC 24           // approx candidates per (q, chunk)
#define POOL (NCHUNK * CPC)      // 528
#define RESC 32          // exact-rescued candidates per q
#define QT3 16

// ---------------- device scratch ----------------
__device__ float g_nasq[MD];                          // -0.125*||mk_m||^2 (exact fp32)
__device__ __nv_bfloat16 g_mkt[(size_t)MPAD * CKD];   // mk^T bf16 [m][c], zero-padded
__device__ float g_vt[(size_t)MD * CHD];              // mem_v^T [m][1536]
__device__ float g_cval[(size_t)QD * POOL];           // approx candidate vals [q][chunk*24]
__device__ int   g_cidx[(size_t)QD * POOL];
__device__ float g_wval[QD * TOPK];
__device__ int   g_widx[QD * TOPK];

// ---------------- mma helper ----------------
__device__ __forceinline__ void mma_bf16(float* c, const uint32_t* a,
                                         uint32_t b0, uint32_t b1) {
    asm volatile(
        "mma.sync.aligned.m16n8k16.row.col.f32.bf16.bf16.f32 "
        "{%0,%1,%2,%3}, {%4,%5,%6,%7}, {%8,%9}, {%0,%1,%2,%3};"
        : "+f"(c[0]), "+f"(c[1]), "+f"(c[2]), "+f"(c[3])
        : "r"(a[0]), "r"(a[1]), "r"(a[2]), "r"(a[3]), "r"(b0), "r"(b1));
}

// ---------------- K0: -0.125*||mk||^2 (exact fp32) ----------------
__global__ void k_asq(const float* __restrict__ mk) {
    int m = blockIdx.x * 256 + threadIdx.x;
    if (m >= MD) return;
    float s = 0.f;
    #pragma unroll
    for (int c = 0; c < CKD; c++) {
        float v = mk[c * MD + m];
        s += v * v;
    }
    g_nasq[m] = -(s * 0.125f);
}

// ---------------- KT: mem_v transpose [1536][M] -> [M][1536] ----------------
__global__ void k_transpose(const float* __restrict__ v) {
    __shared__ float tile[32][33];
    int m0 = blockIdx.x * 32, c0 = blockIdx.y * 32;
    int tx = threadIdx.x, ty = threadIdx.y;
    #pragma unroll
    for (int i = ty; i < 32; i += 8) {
        int m = m0 + tx;
        tile[i][tx] = (m < MD) ? v[(size_t)(c0 + i) * MD + m] : 0.f;
    }
    __syncthreads();
    #pragma unroll
    for (int i = ty; i < 32; i += 8) {
        int m = m0 + i;
        if (m < MD) g_vt[(size_t)m * CHD + c0 + tx] = tile[tx][i];
    }
}

// ---------------- KM: mk transpose + bf16 -> g_mkt [MPAD][64] ----------------
__global__ void k_mkt(const float* __restrict__ mk) {
    __shared__ float tile[32][33];
    int m0 = blockIdx.x * 32, c0 = blockIdx.y * 32;
    int tx = threadIdx.x, ty = threadIdx.y;
    #pragma unroll
    for (int i = ty; i < 32; i += 8) {
        int m = m0 + tx;
        tile[i][tx] = (m < MD) ? mk[(size_t)(c0 + i) * MD + m] : 0.f;
    }
    __syncthreads();
    #pragma unroll
    for (int i = ty; i < 32; i += 8) {
        int m = m0 + i;
        g_mkt[(size_t)m * CKD + c0 + tx] = __float2bfloat16(tile[tx][i]);
    }
}

// ---------------- K1: bf16 mma.sync filter GEMM + per-chunk approx top-24 ----
// smem byte offsets
#define SB_AFF   0                      // fp32 aff [128][68] = 34816 B; UNION qk bf16 [128][68]
#define SB_B     34816                  // 2 x bf16 [64][72] = 2*9216
#define SB_NASQ  53248                  // 2 x 64 f
#define SB_LV    53760                  // 128*24 f
#define SB_LI    66048                  // 128*24 int
#define SB_TOTAL 78336

__global__ void __launch_bounds__(256, 2) k_aff_topk(const float* __restrict__ qk) {
    extern __shared__ char sm[];
    float*          aff   = (float*)(sm + SB_AFF);            // [128][68]
    __nv_bfloat16*  qkb   = (__nv_bfloat16*)(sm + SB_AFF);    // [128][68] (staging union)
    __nv_bfloat16*  smB   = (__nv_bfloat16*)(sm + SB_B);      // [2][64][72]
    float*          nasq2 = (float*)(sm + SB_NASQ);           // [2][64]
    float*          lv    = (float*)(sm + SB_LV);             // [128][24]
    int*            li    = (int*)(sm + SB_LI);

    const int tid = threadIdx.x, lane = tid & 31, wid = tid >> 5;
    const int qw = wid >> 1, mw = wid & 1;     // 4 q-warps x 2 m-warps
    const int q0 = blockIdx.x * QT;
    const int chunk = blockIdx.y;
    const int mc0 = chunk * CHUNKP;
    const int iters = (min(CHUNKP, MD - mc0) + MTILE - 1) / MTILE;

    // stage qk tile as bf16 [q][68]
    for (int t = tid; t < CKD * QT; t += 256) {
        int c = t >> 7, j = t & 127;
        int q = q0 + j;
        float v = (q < QD) ? qk[c * QD + q] : 0.f;
        qkb[j * 68 + c] = __float2bfloat16(v);
    }
    // owners init candidate lists
    if (tid < QT) {
        #pragma unroll
        for (int r = 0; r < CPC; r++) { lv[tid * CPC + r] = -3.0e38f; li[tid * CPC + r] = 0; }
    }
    __syncthreads();

    // A fragments resident in registers: afr[Mt][kstep][4]
    uint32_t afr[2][4][4];
    {
        const int r = lane >> 2, t4 = lane & 3;
        #pragma unroll
        for (int Mt = 0; Mt < 2; Mt++) {
            #pragma unroll
            for (int ks = 0; ks < 4; ks++) {
                int qr = qw * 32 + Mt * 16 + r;
                int cc = ks * 16 + 2 * t4;
                afr[Mt][ks][0] = *(const uint32_t*)&qkb[qr * 68 + cc];
                afr[Mt][ks][1] = *(const uint32_t*)&qkb[(qr + 8) * 68 + cc];
                afr[Mt][ks][2] = *(const uint32_t*)&qkb[qr * 68 + cc + 8];
                afr[Mt][ks][3] = *(const uint32_t*)&qkb[(qr + 8) * 68 + cc + 8];
            }
        }
    }
    __syncthreads();  // qkb reads done; aff region reusable

    // B staging (double buffered, coalesced 128B/warp)
    #define STAGE_B(buf, mb) do { \
        const uint32_t* _src = (const uint32_t*)(g_mkt + (size_t)(mb) * CKD); \
        uint32_t* _dst = (uint32_t*)(smB + (buf) * 64 * 72); \
        _Pragma("unroll") \
        for (int _i = 0; _i < 8; _i++) { \
            int _idx = tid + _i * 256; \
            int _m = _idx >> 5, _cp = _idx & 31; \
            _dst[_m * 36 + _cp] = _src[_idx]; \
        } \
        if (tid < 64) { \
            int _mg = (mb) + tid; \
            nasq2[(buf) * 64 + tid] = (_mg < MD) ? g_nasq[_mg] : -1.0e37f; \
        } \
    } while (0)

    STAGE_B(0, mc0);

    float gate = -3.0e38f;
    int buf = 0;

    for (int it = 0; it < iters; it++) {
        __syncthreads();   // B[buf]+nasq ready; previous scan done (aff free)
        const int m_base = mc0 + it * MTILE;

        // mma: warp tile 32q x 32m, K=64
        float acc[2][4][4];
        #pragma unroll
        for (int i = 0; i < 2; i++)
            #pragma unroll
            for (int j = 0; j < 4; j++)
                #pragma unroll
                for (int e = 0; e < 4; e++) acc[i][j][e] = 0.f;

        const uint32_t* Bb = (const uint32_t*)smB + buf * 64 * 36;
        #pragma unroll
        for (int ks = 0; ks < 4; ks++) {
            #pragma unroll
            for (int Nt = 0; Nt < 4; Nt++) {
                int nl = mw * 32 + Nt * 8 + (lane >> 2);
                uint32_t b0 = Bb[nl * 36 + ks * 8 + (lane & 3)];
                uint32_t b1 = Bb[nl * 36 + ks * 8 + (lane & 3) + 4];
                mma_bf16(acc[0][Nt], afr[0][ks], b0, b1);
                mma_bf16(acc[1][Nt], afr[1][ks], b0, b1);
            }
        }

        // prefetch next B while aff epilogue runs
        if (it + 1 < iters) STAGE_B(buf ^ 1, m_base + MTILE);

        // epilogue: aff = 0.25*dot + (-0.125*asq), store fp32 rows [q][68]
        {
            const int r = lane >> 2, t4 = lane & 3;
            #pragma unroll
            for (int Mt = 0; Mt < 2; Mt++) {
                int qr = qw * 32 + Mt * 16 + r;
                #pragma unroll
                for (int Nt = 0; Nt < 4; Nt++) {
                    int ml = mw * 32 + Nt * 8 + 2 * t4;
                    float2 nn = *(const float2*)&nasq2[buf * 64 + ml];
                    float2 v0, v1;
                    v0.x = 0.25f * acc[Mt][Nt][0] + nn.x;
                    v0.y = 0.25f * acc[Mt][Nt][1] + nn.y;
                    v1.x = 0.25f * acc[Mt][Nt][2] + nn.x;
                    v1.y = 0.25f * acc[Mt][Nt][3] + nn.y;
                    *(float2*)&aff[qr * 68 + ml] = v0;
                    *(float2*)&aff[(qr + 8) * 68 + ml] = v1;
                }
            }
        }
        __syncthreads();   // aff complete

        // 128 owner threads: gated scan of own q row + sorted insert (deterministic)
        if (tid < QT) {
            const float* arow = aff + tid * 68;
            float* Lv = lv + tid * CPC;
            int*   Li = li + tid * CPC;
            #pragma unroll 4
            for (int j = 0; j < 16; j++) {
                float4 v4 = *(const float4*)(arow + j * 4);
                #pragma unroll
                for (int e = 0; e < 4; e++) {
                    float v = (e == 0) ? v4.x : (e == 1) ? v4.y : (e == 2) ? v4.z : v4.w;
                    if (v > gate) {
                        int mg = m_base + j * 4 + e;
                        int p = CPC - 1;
                        while (p > 0 && (v > Lv[p - 1] || (v == Lv[p - 1] && mg < Li[p - 1]))) {
                            Lv[p] = Lv[p - 1]; Li[p] = Li[p - 1]; p--;
                        }
                        Lv[p] = v; Li[p] = mg;
                        gate = Lv[CPC - 1];
                    }
                }
            }
        }
        buf ^= 1;
    }

    // writeout approx candidate lists [q][chunk][24]
    if (tid < QT) {
        int q = q0 + tid;
        if (q < QD) {
            size_t ob = ((size_t)q * NCHUNK + chunk) * CPC;
            #pragma unroll
            for (int r = 0; r < CPC; r++) {
                g_cval[ob + r] = lv[tid * CPC + r];
                g_cidx[ob + r] = li[tid * CPC + r];
            }
        }
    }
}

// ---------------- K2: exact fp32 rescue + top-20 + softmax -------------------
#define NE 17    // ceil(POOL/32)
__global__ void k_rescue(const float* __restrict__ qk, const float* __restrict__ mk) {
    __shared__ float pv[8][POOL];
    __shared__ int   pidx[8][POOL];
    __shared__ float qcol[8][CKD];
    __shared__ float kv[8][RESC];
    __shared__ int   ki[8][RESC];

    int w = threadIdx.x >> 5, lane = threadIdx.x & 31;
    int q = blockIdx.x * 8 + w;
    if (q >= QD) return;

    qcol[w][lane] = qk[lane * QD + q];
    qcol[w][lane + 32] = qk[(lane + 32) * QD + q];
    const float* cv = g_cval + (size_t)q * POOL;
    const int*   ci = g_cidx + (size_t)q * POOL;
    for (int t = lane; t < POOL; t += 32) { pv[w][t] = cv[t]; pidx[w][t] = ci[t]; }
    __syncwarp();

    // approx rank over 528-pool (rank-count, strict total order)
    float ov[NE]; int oi[NE], ar[NE];
    #pragma unroll
    for (int r = 0; r < NE; r++) {
        int t = lane + (r << 5);
        if (t < POOL) { ov[r] = pv[w][t]; oi[r] = pidx[w][t]; }
        else          { ov[r] = -3.4e38f; oi[r] = 0x7fffffff; }
        ar[r] = 0;
    }
    for (int k = 0; k < POOL; k++) {
        float vk = pv[w][k];
        int   ik = pidx[w][k];
        #pragma unroll
        for (int r = 0; r < NE; r++)
            ar[r] += (vk > ov[r] || (vk == ov[r] && ik < oi[r])) ? 1 : 0;
    }

    // exact fp32 affinity for approx-top-32
    #pragma unroll
    for (int r = 0; r < NE; r++) {
        if (ar[r] < RESC && (lane + (r << 5)) < POOL) {
            int m = oi[r];
            float dot = 0.f;
            #pragma unroll 8
            for (int c = 0; c < CKD; c++) dot += mk[(size_t)c * MD + m] * qcol[w][c];
            kv[w][ar[r]] = 0.25f * dot + g_nasq[m];
            ki[w][ar[r]] = m;
        }
    }
    __syncwarp();

    // exact top-20 among 32 + softmax
    float v = kv[w][lane];
    int   i = ki[w][lane];
    int rank = 0;
    #pragma unroll
    for (int k = 0; k < RESC; k++) {
        float vk = kv[w][k];
        int   ik = ki[w][k];
        rank += (vk > v || (vk == v && ik < i)) ? 1 : 0;
    }
    float mx = (rank < TOPK) ? v : -3.4e38f;
    #pragma unroll
    for (int s = 16; s > 0; s >>= 1) {
        float o = __shfl_xor_sync(0xffffffffu, mx, s);
        if (o > mx) mx = o;
    }
    float e = (rank < TOPK) ? expf(v - mx) : 0.f;
    float sum = e;
    #pragma unroll
    for (int s = 16; s > 0; s >>= 1) sum += __shfl_xor_sync(0xffffffffu, sum, s);
    if (rank < TOPK) {
        g_wval[q * TOPK + rank] = e / sum;
        g_widx[q * TOPK + rank] = i;
    }
}

// ---------------- K3: sparse readout ----------------
__global__ void k_readout(float* __restrict__ out) {
    __shared__ float sw[QT3 * TOPK];
    __shared__ int   si[QT3 * TOPK];
    int q0 = blockIdx.x * QT3;
    int ch = blockIdx.y * 256 + threadIdx.x;
    for (int t = threadIdx.x; t < QT3 * TOPK; t += 256) {
        int q = q0 + t / TOPK;
        if (q < QD) {
            sw[t] = g_wval[q * TOPK + (t % TOPK)];
            si[t] = g_widx[q * TOPK + (t % TOPK)];
        } else { sw[t] = 0.f; si[t] = 0; }
    }
    __syncthreads();

    float acc[QT3];
    #pragma unroll
    for (int j = 0; j < QT3; j++) acc[j] = 0.f;
    #pragma unroll
    for (int k = 0; k < TOPK; k++) {
        #pragma unroll
        for (int j = 0; j < QT3; j++)
            acc[j] += sw[j * TOPK + k] * g_vt[(size_t)si[j * TOPK + k] * CHD + ch];
    }
    if (q0 + QT3 <= QD) {
        float4* o4 = (float4*)(out + (size_t)ch * QD + q0);
        #pragma unroll
        for (int jj = 0; jj < QT3 / 4; jj++)
            o4[jj] = make_float4(acc[jj * 4], acc[jj * 4 + 1], acc[jj * 4 + 2], acc[jj * 4 + 3]);
    } else {
        #pragma unroll
        for (int j = 0; j < QT3; j++) {
            int q = q0 + j;
            if (q < QD) out[(size_t)ch * QD + q] = acc[j];
        }
    }
}

// ---------------- launch ----------------
extern "C" void kernel_launch(void* const* d_in, const int* in_sizes, int n_in,
                              void* d_out, int out_size) {
    const float* qk = (const float*)d_in[0];   // [64][1620]
    const float* mk = (const float*)d_in[1];   // [64][32400]
    const float* mv = (const float*)d_in[2];   // [1536][32400]
    float* out = (float*)d_out;                // [1536][1620]
    (void)in_sizes; (void)n_in; (void)out_size;

    k_asq<<<(MD + 255) / 256, 256>>>(mk);                                    // 1
    k_transpose<<<dim3((MD + 31) / 32, CHD / 32), dim3(32, 8)>>>(mv);        // 2
    k_mkt<<<dim3(MPAD / 32, CKD / 32), dim3(32, 8)>>>(mk);                   // 3

    cudaFuncSetAttribute(k_aff_topk, cudaFuncAttributeMaxDynamicSharedMemorySize, SB_TOTAL);
    k_aff_topk<<<dim3(NQB, NCHUNK), 256, SB_TOTAL>>>(qk);                    // 4 (ncu slot)

    k_rescue<<<(QD + 7) / 8, 256>>>(qk, mk);                                 // 5
    k_readout<<<dim3((QD + QT3 - 1) / QT3, CHD / 256), 256>>>(out);          // 6
}

// round 7
// speedup vs baseline: 4.1492x; 4.1492x over previous
#include <cuda_runtime.h>
#include <cuda_bf16.h>
#include <math.h>
#include <stdint.h>

// ---------------- problem constants ----------------
#define CKD 64
#define QD 1620          // H*W
#define MD 32400
#define TOPK 20
#define CHD 1536         // OD*CVD

// ---------------- K1 tiling ----------------
#define QT 128           // q per block
#define MTILE 64         // m per iteration
#define NQB 13           // 13*128 = 1664 >= 1620
#define NCHUNK 22
#define CHUNKP 1536      // m per chunk
#define ITERS1 24        // CHUNKP / MTILE
#define MPAD (NCHUNK * CHUNKP)   // 33792
#define LSZ 12           // register list size per scanner (2 scanners/q)
#define CPC 24           // candidates per (q, chunk) = 2*LSZ
#define POOL (NCHUNK * CPC)      // 528
#define RESC 32
#define NE 17            // ceil(POOL/32)
#define QT3 16

// ---------------- device scratch ----------------
__device__ float g_nasq[MD];                          // -0.125*||mk_m||^2 (exact fp32)
__device__ __nv_bfloat16 g_mkt[(size_t)MPAD * CKD];   // mk^T bf16 [m][c], zero-padded
__device__ float g_vt[(size_t)MD * CHD];              // mem_v^T [m][1536]
__device__ float g_cval[(size_t)QD * POOL];
__device__ int   g_cidx[(size_t)QD * POOL];
__device__ float g_wval[QD * TOPK];
__device__ int   g_widx[QD * TOPK];

// ---------------- mma helper ----------------
__device__ __forceinline__ void mma_bf16(float* c, const uint32_t* a,
                                         uint32_t b0, uint32_t b1) {
    asm volatile(
        "mma.sync.aligned.m16n8k16.row.col.f32.bf16.bf16.f32 "
        "{%0,%1,%2,%3}, {%4,%5,%6,%7}, {%8,%9}, {%0,%1,%2,%3};"
        : "+f"(c[0]), "+f"(c[1]), "+f"(c[2]), "+f"(c[3])
        : "r"(a[0]), "r"(a[1]), "r"(a[2]), "r"(a[3]), "r"(b0), "r"(b1));
}

// ---------------- K0: -0.125*||mk||^2 ----------------
__global__ void k_asq(const float* __restrict__ mk) {
    int m = blockIdx.x * 256 + threadIdx.x;
    if (m >= MD) return;
    float s = 0.f;
    #pragma unroll
    for (int c = 0; c < CKD; c++) {
        float v = mk[c * MD + m];
        s += v * v;
    }
    g_nasq[m] = -(s * 0.125f);
}

// ---------------- KT: mem_v transpose [1536][M] -> [M][1536] ----------------
__global__ void k_transpose(const float* __restrict__ v) {
    __shared__ float tile[32][33];
    int m0 = blockIdx.x * 32, c0 = blockIdx.y * 32;
    int tx = threadIdx.x, ty = threadIdx.y;
    #pragma unroll
    for (int i = ty; i < 32; i += 8) {
        int m = m0 + tx;
        tile[i][tx] = (m < MD) ? v[(size_t)(c0 + i) * MD + m] : 0.f;
    }
    __syncthreads();
    #pragma unroll
    for (int i = ty; i < 32; i += 8) {
        int m = m0 + i;
        if (m < MD) g_vt[(size_t)m * CHD + c0 + tx] = tile[tx][i];
    }
}

// ---------------- KM: mk transpose + bf16 -> g_mkt [MPAD][64] ----------------
__global__ void k_mkt(const float* __restrict__ mk) {
    __shared__ float tile[32][33];
    int m0 = blockIdx.x * 32, c0 = blockIdx.y * 32;
    int tx = threadIdx.x, ty = threadIdx.y;
    #pragma unroll
    for (int i = ty; i < 32; i += 8) {
        int m = m0 + tx;
        tile[i][tx] = (m < MD) ? mk[(size_t)(c0 + i) * MD + m] : 0.f;
    }
    __syncthreads();
    #pragma unroll
    for (int i = ty; i < 32; i += 8) {
        int m = m0 + i;
        g_mkt[(size_t)m * CKD + c0 + tx] = __float2bfloat16(tile[tx][i]);
    }
}

// ---------------- K1: bf16 mma filter + register-list per-chunk top-24 -------
// smem byte offsets
#define SB_AFF   0                       // fp32 aff [128][68] = 34816
#define SB_QKB   34816                   // bf16 qk [128][68] = 17408 (persistent)
#define SB_B     52224                   // bf16 [2][64][72] = 18432
#define SB_NASQ  70656                   // 2 x 64 f = 512
#define SB_TOTAL 71168

__global__ void __launch_bounds__(256, 2) k_aff_topk(const float* __restrict__ qk) {
    extern __shared__ char sm[];
    float*          aff   = (float*)(sm + SB_AFF);
    __nv_bfloat16*  qkb   = (__nv_bfloat16*)(sm + SB_QKB);
    __nv_bfloat16*  smB   = (__nv_bfloat16*)(sm + SB_B);
    float*          nasq2 = (float*)(sm + SB_NASQ);

    const int tid = threadIdx.x, lane = tid & 31, wid = tid >> 5;
    const int qw = wid >> 1, mw = wid & 1;     // 4 q-warps x 2 m-warps
    const int q0 = blockIdx.x * QT;
    const int chunk = blockIdx.y;
    const int mc0 = chunk * CHUNKP;

    // stage qk tile as bf16 [q][68] (persistent for all tiles)
    for (int t = tid; t < CKD * QT; t += 256) {
        int c = t >> 7, j = t & 127;
        int q = q0 + j;
        float v = (q < QD) ? qk[c * QD + q] : 0.f;
        qkb[j * 68 + c] = __float2bfloat16(v);
    }

    // scanner state: 2 scanners per q, register-resident sorted lists
    const int sq = tid >> 1, shalf = tid & 1;
    float Lv[LSZ];
    int   Li[LSZ];
    #pragma unroll
    for (int i = 0; i < LSZ; i++) { Lv[i] = -3.0e38f; Li[i] = 0; }
    float gate = -3.0e38f;

    // B staging (double buffered)
    #define STAGE_B(bu, mb) do { \
        const uint32_t* _src = (const uint32_t*)(g_mkt + (size_t)(mb) * CKD); \
        uint32_t* _dst = (uint32_t*)(smB + (bu) * 64 * 72); \
        _Pragma("unroll") \
        for (int _i = 0; _i < 8; _i++) { \
            int _idx = tid + _i * 256; \
            int _m = _idx >> 5, _cp = _idx & 31; \
            _dst[_m * 36 + _cp] = _src[_idx]; \
        } \
        if (tid < 64) { \
            int _mg = (mb) + tid; \
            nasq2[(bu) * 64 + tid] = (_mg < MD) ? g_nasq[_mg] : -1.0e37f; \
        } \
    } while (0)

    STAGE_B(0, mc0);
    int buf = 0;
    const int r8 = lane >> 2, t4 = lane & 3;

    for (int it = 0; it < ITERS1; it++) {
        __syncthreads();   // B[buf]+nasq ready; previous scan done (aff free)
        const int m_base = mc0 + it * MTILE;

        // A fragments from persistent qkb smem
        uint32_t afr[2][4][4];
        #pragma unroll
        for (int Mt = 0; Mt < 2; Mt++) {
            #pragma unroll
            for (int ks = 0; ks < 4; ks++) {
                int qr = qw * 32 + Mt * 16 + r8;
                int cc = ks * 16 + 2 * t4;
                afr[Mt][ks][0] = *(const uint32_t*)&qkb[qr * 68 + cc];
                afr[Mt][ks][1] = *(const uint32_t*)&qkb[(qr + 8) * 68 + cc];
                afr[Mt][ks][2] = *(const uint32_t*)&qkb[qr * 68 + cc + 8];
                afr[Mt][ks][3] = *(const uint32_t*)&qkb[(qr + 8) * 68 + cc + 8];
            }
        }

        // warp tile 32q x 32m, K=64
        float acc[2][4][4];
        #pragma unroll
        for (int i = 0; i < 2; i++)
            #pragma unroll
            for (int j = 0; j < 4; j++)
                #pragma unroll
                for (int e = 0; e < 4; e++) acc[i][j][e] = 0.f;

        const uint32_t* Bb = (const uint32_t*)smB + buf * 64 * 36;
        #pragma unroll
        for (int ks = 0; ks < 4; ks++) {
            #pragma unroll
            for (int Nt = 0; Nt < 4; Nt++) {
                int nl = mw * 32 + Nt * 8 + r8;
                uint32_t b0 = Bb[nl * 36 + ks * 8 + t4];
                uint32_t b1 = Bb[nl * 36 + ks * 8 + t4 + 4];
                mma_bf16(acc[0][Nt], afr[0][ks], b0, b1);
                mma_bf16(acc[1][Nt], afr[1][ks], b0, b1);
            }
        }

        // prefetch next B while epilogue runs
        if (it + 1 < ITERS1) STAGE_B(buf ^ 1, m_base + MTILE);

        // epilogue: aff = 0.25*dot + (-0.125*asq)
        #pragma unroll
        for (int Mt = 0; Mt < 2; Mt++) {
            int qr = qw * 32 + Mt * 16 + r8;
            #pragma unroll
            for (int Nt = 0; Nt < 4; Nt++) {
                int ml = mw * 32 + Nt * 8 + 2 * t4;
                float2 nn = *(const float2*)&nasq2[buf * 64 + ml];
                float2 v0, v1;
                v0.x = 0.25f * acc[Mt][Nt][0] + nn.x;
                v0.y = 0.25f * acc[Mt][Nt][1] + nn.y;
                v1.x = 0.25f * acc[Mt][Nt][2] + nn.x;
                v1.y = 0.25f * acc[Mt][Nt][3] + nn.y;
                *(float2*)&aff[qr * 68 + ml] = v0;
                *(float2*)&aff[(qr + 8) * 68 + ml] = v1;
            }
        }
        __syncthreads();   // aff complete

        // scan: all 256 threads; thread owns (q = tid>>1, half = tid&1), 32 values
        {
            const float* arow = aff + sq * 68 + shalf * 32;
            const int mb2 = m_base + shalf * 32;
            #pragma unroll
            for (int j = 0; j < 8; j++) {
                float4 v4 = *(const float4*)(arow + j * 4);
                #pragma unroll
                for (int e = 0; e < 4; e++) {
                    float v = (e == 0) ? v4.x : (e == 1) ? v4.y : (e == 2) ? v4.z : v4.w;
                    if (v > gate) {
                        float cv = v;
                        int cm = mb2 + j * 4 + e;
                        #pragma unroll
                        for (int i = 0; i < LSZ; i++) {
                            bool sw = (cv > Lv[i]) || (cv == Lv[i] && cm < Li[i]);
                            float tv = Lv[i]; int tm2 = Li[i];
                            if (sw) { Lv[i] = cv; Li[i] = tm2 >= 0 ? cm : cm; Li[i] = cm; cv = tv; cm = tm2; }
                        }
                        gate = Lv[LSZ - 1];
                    }
                }
            }
        }
        buf ^= 1;
    }

    // writeout candidate lists: [q][chunk][24] (half*12 + r)
    {
        int q = q0 + sq;
        if (q < QD) {
            size_t ob = ((size_t)q * NCHUNK + chunk) * CPC + shalf * LSZ;
            #pragma unroll
            for (int r = 0; r < LSZ; r++) {
                g_cval[ob + r] = Lv[r];
                g_cidx[ob + r] = Li[r];
            }
        }
    }
}

// ---------------- K2: warp-extract top-32, exact fp32 rescue, softmax --------
__device__ __forceinline__ uint64_t sortkey(float v, int idx) {
    uint32_t b = __float_as_uint(v);
    b = (b & 0x80000000u) ? ~b : (b | 0x80000000u);   // order-preserving float map
    return ((uint64_t)b << 32) | (uint32_t)(0xFFFFFFFFu - (uint32_t)idx);
}

__global__ void k_rescue(const float* __restrict__ qk, const float* __restrict__ mk) {
    __shared__ float pv[8][POOL];
    __shared__ int   pidx[8][POOL];
    __shared__ float qcol[8][CKD];

    int w = threadIdx.x >> 5, lane = threadIdx.x & 31;
    int q = blockIdx.x * 8 + w;
    if (q >= QD) return;

    qcol[w][lane] = qk[lane * QD + q];
    qcol[w][lane + 32] = qk[(lane + 32) * QD + q];
    const float* cv = g_cval + (size_t)q * POOL;
    const int*   ci = g_cidx + (size_t)q * POOL;
    for (int t = lane; t < POOL; t += 32) { pv[w][t] = cv[t]; pidx[w][t] = ci[t]; }
    __syncwarp();

    // local best among own NE entries
    uint64_t bestk = 0;
    #pragma unroll
    for (int r = 0; r < NE; r++) {
        int t = lane + (r << 5);
        if (t < POOL) {
            uint64_t k = sortkey(pv[w][t], pidx[w][t]);
            if (k > bestk) bestk = k;
        }
    }

    // 32 rounds of warp argmax extraction; lane r keeps round-r winner
    int myM = 0;
    for (int round = 0; round < RESC; round++) {
        uint64_t k = bestk;
        #pragma unroll
        for (int s = 16; s > 0; s >>= 1) {
            uint64_t o = __shfl_xor_sync(0xffffffffu, k, s);
            if (o > k) k = o;
        }
        if (lane == round) myM = (int)(0xFFFFFFFFu - (uint32_t)k);
        if (k == bestk) {   // unique owner consumes + rescans
            uint64_t nb = 0;
            #pragma unroll
            for (int r = 0; r < NE; r++) {
                int t = lane + (r << 5);
                if (t < POOL) {
                    uint64_t kk = sortkey(pv[w][t], pidx[w][t]);
                    if (kk == k) { pv[w][t] = -3.4e38f; pidx[w][t] = 0x7FFFFFFF; }
                    else if (kk > nb) nb = kk;
                }
            }
            bestk = nb;
        }
    }

    // exact fp32 affinity for my candidate
    float dot = 0.f;
    #pragma unroll 16
    for (int c = 0; c < CKD; c++) dot += mk[(size_t)c * MD + myM] * qcol[w][c];
    float ev = 0.25f * dot + g_nasq[myM];

    // rank among the 32 (val desc, idx asc)
    int rank = 0;
    #pragma unroll
    for (int k = 0; k < RESC; k++) {
        float vk = __shfl_sync(0xffffffffu, ev, k);
        int   ik = __shfl_sync(0xffffffffu, myM, k);
        rank += (vk > ev || (vk == ev && ik < myM)) ? 1 : 0;
    }
    float mx = (rank < TOPK) ? ev : -3.4e38f;
    #pragma unroll
    for (int s = 16; s > 0; s >>= 1) {
        float o = __shfl_xor_sync(0xffffffffu, mx, s);
        if (o > mx) mx = o;
    }
    float e = (rank < TOPK) ? expf(ev - mx) : 0.f;
    float sum = e;
    #pragma unroll
    for (int s = 16; s > 0; s >>= 1) sum += __shfl_xor_sync(0xffffffffu, sum, s);
    if (rank < TOPK) {
        g_wval[q * TOPK + rank] = e / sum;
        g_widx[q * TOPK + rank] = myM;
    }
}

// ---------------- K3: sparse readout ----------------
__global__ void k_readout(float* __restrict__ out) {
    __shared__ float sw[QT3 * TOPK];
    __shared__ int   si[QT3 * TOPK];
    int q0 = blockIdx.x * QT3;
    int ch = blockIdx.y * 256 + threadIdx.x;
    for (int t = threadIdx.x; t < QT3 * TOPK; t += 256) {
        int q = q0 + t / TOPK;
        if (q < QD) {
            sw[t] = g_wval[q * TOPK + (t % TOPK)];
            si[t] = g_widx[q * TOPK + (t % TOPK)];
        } else { sw[t] = 0.f; si[t] = 0; }
    }
    __syncthreads();

    float acc[QT3];
    #pragma unroll
    for (int j = 0; j < QT3; j++) acc[j] = 0.f;
    #pragma unroll
    for (int k = 0; k < TOPK; k++) {
        #pragma unroll
        for (int j = 0; j < QT3; j++)
            acc[j] += sw[j * TOPK + k] * g_vt[(size_t)si[j * TOPK + k] * CHD + ch];
    }
    if (q0 + QT3 <= QD) {
        float4* o4 = (float4*)(out + (size_t)ch * QD + q0);
        #pragma unroll
        for (int jj = 0; jj < QT3 / 4; jj++)
            o4[jj] = make_float4(acc[jj * 4], acc[jj * 4 + 1], acc[jj * 4 + 2], acc[jj * 4 + 3]);
    } else {
        #pragma unroll
        for (int j = 0; j < QT3; j++) {
            int q = q0 + j;
            if (q < QD) out[(size_t)ch * QD + q] = acc[j];
        }
    }
}

// ---------------- launch ----------------
extern "C" void kernel_launch(void* const* d_in, const int* in_sizes, int n_in,
                              void* d_out, int out_size) {
    const float* qk = (const float*)d_in[0];   // [64][1620]
    const float* mk = (const float*)d_in[1];   // [64][32400]
    const float* mv = (const float*)d_in[2];   // [1536][32400]
    float* out = (float*)d_out;                // [1536][1620]
    (void)in_sizes; (void)n_in; (void)out_size;

    k_asq<<<(MD + 255) / 256, 256>>>(mk);                                    // 1
    k_transpose<<<dim3((MD + 31) / 32, CHD / 32), dim3(32, 8)>>>(mv);        // 2
    k_mkt<<<dim3(MPAD / 32, CKD / 32), dim3(32, 8)>>>(mk);                   // 3

    cudaFuncSetAttribute(k_aff_topk, cudaFuncAttributeMaxDynamicSharedMemorySize, SB_TOTAL);
    k_aff_topk<<<dim3(NQB, NCHUNK), 256, SB_TOTAL>>>(qk);                    // 4 (ncu slot)

    k_rescue<<<(QD + 7) / 8, 256>>>(qk, mk);                                 // 5
    k_readout<<<dim3((QD + QT3 - 1) / QT3, CHD / 256), 256>>>(out);          // 6
}

// round 9
// speedup vs baseline: 12.4357x; 2.9972x over previous
#include <cuda_runtime.h>
#include <cuda_bf16.h>
#include <math.h>
#include <stdint.h>

// ---------------- problem constants ----------------
#define CKD 64
#define QD 1620          // H*W
#define MD 32400
#define TOPK 20
#define CHD 1536         // OD*CVD

// ---------------- filter tiling ----------------
#define QT 128           // q per block
#define MTILE 64         // m per iteration
#define NQB 13           // 13*128 = 1664 >= 1620
#define NCHUNK 22
#define CHUNKP 1536      // m per chunk
#define ITERS1 24        // CHUNKP / MTILE
#define MPAD (NCHUNK * CHUNKP)   // 33792
#define HCAP 512         // per-q hit capacity
#define QT3 16

// ---------------- device scratch ----------------
__device__ float g_nasq[MD];                          // -0.125*||mk_m||^2 (exact fp32)
__device__ __nv_bfloat16 g_mkt[(size_t)MPAD * CKD];   // mk^T bf16 [m][c], zero-padded
__device__ float g_mktf[(size_t)MD * CKD];            // mk^T fp32 [m][c] (exact)
__device__ float g_vt[(size_t)MD * CHD];              // mem_v^T [m][1536]
__device__ unsigned g_chunkmax[NQB * QT * NCHUNK];    // encoded per-(q,chunk) max
__device__ float g_thresh[QD];
__device__ int   g_hcnt[QD];
__device__ int   g_hits[(size_t)QD * HCAP];
__device__ float g_wval[QD * TOPK];
__device__ int   g_widx[QD * TOPK];

// order-preserving float<->uint map (unsigned domain!)
__device__ __forceinline__ unsigned encf(float v) {
    unsigned b = __float_as_uint(v);
    return (b & 0x80000000u) ? ~b : (b | 0x80000000u);
}
__device__ __forceinline__ float decf(unsigned u) {
    unsigned b = (u & 0x80000000u) ? (u & 0x7FFFFFFFu) : ~u;
    return __uint_as_float(b);
}

// ---------------- mma helper ----------------
__device__ __forceinline__ void mma_bf16(float* c, const uint32_t* a,
                                         uint32_t b0, uint32_t b1) {
    asm volatile(
        "mma.sync.aligned.m16n8k16.row.col.f32.bf16.bf16.f32 "
        "{%0,%1,%2,%3}, {%4,%5,%6,%7}, {%8,%9}, {%0,%1,%2,%3};"
        : "+f"(c[0]), "+f"(c[1]), "+f"(c[2]), "+f"(c[3])
        : "r"(a[0]), "r"(a[1]), "r"(a[2]), "r"(a[3]), "r"(b0), "r"(b1));
}

// ---------------- K0: -0.125*||mk||^2 ----------------
__global__ void k_asq(const float* __restrict__ mk) {
    int m = blockIdx.x * 256 + threadIdx.x;
    if (m >= MD) return;
    float s = 0.f;
    #pragma unroll
    for (int c = 0; c < CKD; c++) {
        float v = mk[c * MD + m];
        s += v * v;
    }
    g_nasq[m] = -(s * 0.125f);
}

// ---------------- KT: mem_v transpose [1536][M] -> [M][1536] ----------------
__global__ void k_transpose(const float* __restrict__ v) {
    __shared__ float tile[32][33];
    int m0 = blockIdx.x * 32, c0 = blockIdx.y * 32;
    int tx = threadIdx.x, ty = threadIdx.y;
    #pragma unroll
    for (int i = ty; i < 32; i += 8) {
        int m = m0 + tx;
        tile[i][tx] = (m < MD) ? v[(size_t)(c0 + i) * MD + m] : 0.f;
    }
    __syncthreads();
    #pragma unroll
    for (int i = ty; i < 32; i += 8) {
        int m = m0 + i;
        if (m < MD) g_vt[(size_t)m * CHD + c0 + tx] = tile[tx][i];
    }
}

// ---------------- KM: mk transpose -> bf16 g_mkt + fp32 g_mktf ---------------
__global__ void k_mkt(const float* __restrict__ mk) {
    __shared__ float tile[32][33];
    int m0 = blockIdx.x * 32, c0 = blockIdx.y * 32;
    int tx = threadIdx.x, ty = threadIdx.y;
    #pragma unroll
    for (int i = ty; i < 32; i += 8) {
        int m = m0 + tx;
        tile[i][tx] = (m < MD) ? mk[(size_t)(c0 + i) * MD + m] : 0.f;
    }
    __syncthreads();
    #pragma unroll
    for (int i = ty; i < 32; i += 8) {
        int m = m0 + i;
        float v = tile[tx][i];
        g_mkt[(size_t)m * CKD + c0 + tx] = __float2bfloat16(v);
        if (m < MD) g_mktf[(size_t)m * CKD + c0 + tx] = v;
    }
}

// ---------------- filter GEMM common smem layout ----------------
#define SB_QKB   0                       // bf16 qk [128][68] = 17408
#define SB_B     17408                   // uint32 [2][64][36] = 18432
#define SB_NASQ  35840                   // 2 x 64 f = 512
#define SB_RED   36352                   // 128 unsigned = 512
#define SB_TOTAL 36864

#define STAGE_B(bu, mb) do { \
    const uint32_t* _src = (const uint32_t*)(g_mkt + (size_t)(mb) * CKD); \
    uint32_t* _dst = (uint32_t*)(sm + SB_B) + (bu) * 64 * 36; \
    _Pragma("unroll") \
    for (int _i = 0; _i < 8; _i++) { \
        int _idx = tid + _i * 256; \
        int _m = _idx >> 5, _cp = _idx & 31; \
        _dst[_m * 36 + _cp] = _src[_idx]; \
    } \
    if (tid < 64) { \
        int _mg = (mb) + tid; \
        nasq2[(bu) * 64 + tid] = (_mg < MD) ? g_nasq[_mg] : -1.0e37f; \
    } \
} while (0)

#define STAGE_QKB() do { \
    for (int t = tid; t < CKD * QT; t += 256) { \
        int c = t >> 7, j = t & 127; \
        int q = q0 + j; \
        float v = (q < QD) ? qk[c * QD + q] : 0.f; \
        qkb[j * 68 + c] = __float2bfloat16(v); \
    } \
} while (0)

#define LOAD_AFR() do { \
    _Pragma("unroll") \
    for (int Mt = 0; Mt < 2; Mt++) { \
        _Pragma("unroll") \
        for (int ks = 0; ks < 4; ks++) { \
            int qr = qw * 32 + Mt * 16 + r8; \
            int cc = ks * 16 + 2 * t4; \
            afr[Mt][ks][0] = *(const uint32_t*)&qkb[qr * 68 + cc]; \
            afr[Mt][ks][1] = *(const uint32_t*)&qkb[(qr + 8) * 68 + cc]; \
            afr[Mt][ks][2] = *(const uint32_t*)&qkb[qr * 68 + cc + 8]; \
            afr[Mt][ks][3] = *(const uint32_t*)&qkb[(qr + 8) * 68 + cc + 8]; \
        } \
    } \
} while (0)

#define DO_MMA(bu) do { \
    const uint32_t* Bb = (const uint32_t*)(sm + SB_B) + (bu) * 64 * 36; \
    _Pragma("unroll") \
    for (int ks = 0; ks < 4; ks++) { \
        _Pragma("unroll") \
        for (int Nt = 0; Nt < 4; Nt++) { \
            int nl = mw * 32 + Nt * 8 + r8; \
            uint32_t b0 = Bb[nl * 36 + ks * 8 + t4]; \
            uint32_t b1 = Bb[nl * 36 + ks * 8 + t4 + 4]; \
            mma_bf16(acc[0][Nt], afr[0][ks], b0, b1); \
            mma_bf16(acc[1][Nt], afr[1][ks], b0, b1); \
        } \
    } \
} while (0)

// ---------------- K1a: filter GEMM -> per-(q,chunk) max ----------------------
__global__ void __launch_bounds__(256, 2) k_affA(const float* __restrict__ qk) {
    extern __shared__ char sm[];
    __nv_bfloat16* qkb = (__nv_bfloat16*)(sm + SB_QKB);
    float* nasq2 = (float*)(sm + SB_NASQ);
    unsigned* red = (unsigned*)(sm + SB_RED);

    const int tid = threadIdx.x, lane = tid & 31, wid = tid >> 5;
    const int qw = wid >> 1, mw = wid & 1;
    const int r8 = lane >> 2, t4 = lane & 3;
    const int q0 = blockIdx.x * QT;
    const int chunk = blockIdx.y;
    const int mc0 = chunk * CHUNKP;

    STAGE_QKB();
    if (tid < QT) red[tid] = 0u;
    __syncthreads();

    uint32_t afr[2][4][4];
    LOAD_AFR();
    STAGE_B(0, mc0);
    __syncthreads();

    float rmax[4] = {-3.0e38f, -3.0e38f, -3.0e38f, -3.0e38f};
    int buf = 0;

    for (int it = 0; it < ITERS1; it++) {
        const int m_base = mc0 + it * MTILE;
        float acc[2][4][4];
        #pragma unroll
        for (int i = 0; i < 2; i++)
            #pragma unroll
            for (int j = 0; j < 4; j++)
                #pragma unroll
                for (int e = 0; e < 4; e++) acc[i][j][e] = 0.f;

        DO_MMA(buf);
        if (it + 1 < ITERS1) STAGE_B(buf ^ 1, m_base + MTILE);

        // epilogue: running max of 0.25*dot + nasq
        #pragma unroll
        for (int Mt = 0; Mt < 2; Mt++) {
            #pragma unroll
            for (int Nt = 0; Nt < 4; Nt++) {
                int ml = mw * 32 + Nt * 8 + 2 * t4;
                float2 nn = *(const float2*)&nasq2[buf * 64 + ml];
                float a0 = fmaxf(0.25f * acc[Mt][Nt][0] + nn.x, 0.25f * acc[Mt][Nt][1] + nn.y);
                float a1 = fmaxf(0.25f * acc[Mt][Nt][2] + nn.x, 0.25f * acc[Mt][Nt][3] + nn.y);
                rmax[2 * Mt + 0] = fmaxf(rmax[2 * Mt + 0], a0);
                rmax[2 * Mt + 1] = fmaxf(rmax[2 * Mt + 1], a1);
            }
        }
        __syncthreads();
        buf ^= 1;
    }

    // reduce across t4 lanes, then across mw warps via smem atomicMax (UNSIGNED!)
    #pragma unroll
    for (int i = 0; i < 4; i++) {
        #pragma unroll
        for (int s = 1; s <= 2; s <<= 1) {
            float o = __shfl_xor_sync(0xffffffffu, rmax[i], s);
            rmax[i] = fmaxf(rmax[i], o);
        }
    }
    if (t4 == 0) {
        #pragma unroll
        for (int i = 0; i < 4; i++) {
            int row = qw * 32 + (i >> 1) * 16 + r8 + (i & 1) * 8;
            atomicMax(&red[row], encf(rmax[i]));
        }
    }
    __syncthreads();
    if (tid < QT) g_chunkmax[(q0 + tid) * NCHUNK + chunk] = red[tid];
}

// ---------------- K2a: threshold = 20th-largest chunk max - margin ----------
__global__ void k_thresh() {
    int q = blockIdx.x * 256 + threadIdx.x;
    if (q >= QD) return;
    // 3rd smallest of 22 encoded values = 20th largest
    unsigned s1 = 0xFFFFFFFFu, s2 = 0xFFFFFFFFu, s3 = 0xFFFFFFFFu;
    #pragma unroll
    for (int c = 0; c < NCHUNK; c++) {
        unsigned u = g_chunkmax[q * NCHUNK + c];
        if (u < s1)      { s3 = s2; s2 = s1; s1 = u; }
        else if (u < s2) { s3 = s2; s2 = u; }
        else if (u < s3) { s3 = u; }
    }
    g_thresh[q] = decf(s3) - 0.0625f;
    g_hcnt[q] = 0;
}

// ---------------- K1b: filter GEMM -> collect hits >= threshold --------------
__global__ void __launch_bounds__(256, 2) k_affB(const float* __restrict__ qk) {
    extern __shared__ char sm[];
    __nv_bfloat16* qkb = (__nv_bfloat16*)(sm + SB_QKB);
    float* nasq2 = (float*)(sm + SB_NASQ);

    const int tid = threadIdx.x, lane = tid & 31, wid = tid >> 5;
    const int qw = wid >> 1, mw = wid & 1;
    const int r8 = lane >> 2, t4 = lane & 3;
    const int q0 = blockIdx.x * QT;
    const int chunk = blockIdx.y;
    const int mc0 = chunk * CHUNKP;

    STAGE_QKB();
    __syncthreads();

    uint32_t afr[2][4][4];
    LOAD_AFR();

    // per-thread row thresholds
    float T[4];
    int qg[4];
    #pragma unroll
    for (int i = 0; i < 4; i++) {
        int row = qw * 32 + (i >> 1) * 16 + r8 + (i & 1) * 8;
        qg[i] = q0 + row;
        T[i] = (qg[i] < QD) ? g_thresh[qg[i]] : 3.4e38f;
    }

    STAGE_B(0, mc0);
    __syncthreads();

    int buf = 0;
    for (int it = 0; it < ITERS1; it++) {
        const int m_base = mc0 + it * MTILE;
        float acc[2][4][4];
        #pragma unroll
        for (int i = 0; i < 2; i++)
            #pragma unroll
            for (int j = 0; j < 4; j++)
                #pragma unroll
                for (int e = 0; e < 4; e++) acc[i][j][e] = 0.f;

        DO_MMA(buf);
        if (it + 1 < ITERS1) STAGE_B(buf ^ 1, m_base + MTILE);

        // epilogue: compare to threshold, push hit indices (rare)
        #pragma unroll
        for (int Mt = 0; Mt < 2; Mt++) {
            #pragma unroll
            for (int Nt = 0; Nt < 4; Nt++) {
                int ml = mw * 32 + Nt * 8 + 2 * t4;
                float2 nn = *(const float2*)&nasq2[buf * 64 + ml];
                float v00 = 0.25f * acc[Mt][Nt][0] + nn.x;
                float v01 = 0.25f * acc[Mt][Nt][1] + nn.y;
                float v10 = 0.25f * acc[Mt][Nt][2] + nn.x;
                float v11 = 0.25f * acc[Mt][Nt][3] + nn.y;
                int i0 = 2 * Mt, i1 = 2 * Mt + 1;
                if (v00 >= T[i0]) {
                    int p = atomicAdd(&g_hcnt[qg[i0]], 1);
                    if (p < HCAP) g_hits[(size_t)qg[i0] * HCAP + p] = m_base + ml;
                }
                if (v01 >= T[i0]) {
                    int p = atomicAdd(&g_hcnt[qg[i0]], 1);
                    if (p < HCAP) g_hits[(size_t)qg[i0] * HCAP + p] = m_base + ml + 1;
                }
                if (v10 >= T[i1]) {
                    int p = atomicAdd(&g_hcnt[qg[i1]], 1);
                    if (p < HCAP) g_hits[(size_t)qg[i1] * HCAP + p] = m_base + ml;
                }
                if (v11 >= T[i1]) {
                    int p = atomicAdd(&g_hcnt[qg[i1]], 1);
                    if (p < HCAP) g_hits[(size_t)qg[i1] * HCAP + p] = m_base + ml + 1;
                }
            }
        }
        __syncthreads();
        buf ^= 1;
    }
}

// ---------------- K2: exact fp32 eval of hits + top-20 + softmax -------------
__global__ void k_rescue(const float* __restrict__ qk) {
    __shared__ int   pool[8][HCAP];
    __shared__ float pval[8][HCAP];
    __shared__ float qcol[8][CKD];

    int w = threadIdx.x >> 5, lane = threadIdx.x & 31;
    int q = blockIdx.x * 8 + w;
    if (q >= QD) return;

    qcol[w][lane] = qk[lane * QD + q];
    qcol[w][lane + 32] = qk[(lane + 32) * QD + q];
    int cnt = g_hcnt[q];
    if (cnt > HCAP) cnt = HCAP;
    const int* hp = g_hits + (size_t)q * HCAP;
    for (int i = lane; i < cnt; i += 32) pool[w][i] = hp[i];
    __syncwarp();

    // exact fp32 affinity for each hit
    for (int i = lane; i < cnt; i += 32) {
        int m = pool[w][i];
        const float4* kr = (const float4*)(g_mktf + (size_t)m * CKD);
        float dot = 0.f;
        #pragma unroll
        for (int c4 = 0; c4 < 16; c4++) {
            float4 kv = kr[c4];
            dot += kv.x * qcol[w][c4 * 4 + 0] + kv.y * qcol[w][c4 * 4 + 1]
                 + kv.z * qcol[w][c4 * 4 + 2] + kv.w * qcol[w][c4 * 4 + 3];
        }
        pval[w][i] = 0.25f * dot + g_nasq[m];
    }
    __syncwarp();

    // per-lane local best over strided entries
    uint64_t bestk = 0;
    for (int i = lane; i < cnt; i += 32) {
        uint64_t k = ((uint64_t)encf(pval[w][i]) << 32) | (uint32_t)(0xFFFFFFFFu - (uint32_t)pool[w][i]);
        if (k > bestk) bestk = k;
    }

    // 20 rounds of warp argmax extraction, with running softmax sum
    float vmax = 0.f, sum = 0.f;
    float myv = 0.f;
    int   myi = 0;
    for (int r = 0; r < TOPK; r++) {
        uint64_t k = bestk;
        #pragma unroll
        for (int s = 16; s > 0; s >>= 1) {
            uint64_t o = __shfl_xor_sync(0xffffffffu, k, s);
            if (o > k) k = o;
        }
        float kv = decf((unsigned)(k >> 32));
        if (r == 0) vmax = kv;
        sum += expf(kv - vmax);
        if (lane == r) { myv = kv; myi = (int)(0xFFFFFFFFu - (uint32_t)k); }
        if (k == bestk && k != 0) {
            // owner consumes + rescans own entries
            uint64_t nb = 0;
            for (int i = lane; i < cnt; i += 32) {
                uint64_t kk = ((uint64_t)encf(pval[w][i]) << 32) | (uint32_t)(0xFFFFFFFFu - (uint32_t)pool[w][i]);
                if (kk == k) pval[w][i] = -3.4e38f;
                else if (kk > nb && kk < k) nb = kk;
            }
            bestk = nb;
        }
    }
    if (lane < TOPK) {
        g_wval[q * TOPK + lane] = expf(myv - vmax) / sum;
        g_widx[q * TOPK + lane] = myi;
    }
}

// ---------------- K3: sparse readout ----------------
__global__ void k_readout(float* __restrict__ out) {
    __shared__ float sw[QT3 * TOPK];
    __shared__ int   si[QT3 * TOPK];
    int q0 = blockIdx.x * QT3;
    int ch = blockIdx.y * 256 + threadIdx.x;
    for (int t = threadIdx.x; t < QT3 * TOPK; t += 256) {
        int q = q0 + t / TOPK;
        if (q < QD) {
            sw[t] = g_wval[q * TOPK + (t % TOPK)];
            si[t] = g_widx[q * TOPK + (t % TOPK)];
        } else { sw[t] = 0.f; si[t] = 0; }
    }
    __syncthreads();

    float acc[QT3];
    #pragma unroll
    for (int j = 0; j < QT3; j++) acc[j] = 0.f;
    #pragma unroll
    for (int k = 0; k < TOPK; k++) {
        #pragma unroll
        for (int j = 0; j < QT3; j++)
            acc[j] += sw[j * TOPK + k] * g_vt[(size_t)si[j * TOPK + k] * CHD + ch];
    }
    if (q0 + QT3 <= QD) {
        float4* o4 = (float4*)(out + (size_t)ch * QD + q0);
        #pragma unroll
        for (int jj = 0; jj < QT3 / 4; jj++)
            o4[jj] = make_float4(acc[jj * 4], acc[jj * 4 + 1], acc[jj * 4 + 2], acc[jj * 4 + 3]);
    } else {
        #pragma unroll
        for (int j = 0; j < QT3; j++) {
            int q = q0 + j;
            if (q < QD) out[(size_t)ch * QD + q] = acc[j];
        }
    }
}

// ---------------- launch ----------------
extern "C" void kernel_launch(void* const* d_in, const int* in_sizes, int n_in,
                              void* d_out, int out_size) {
    const float* qk = (const float*)d_in[0];   // [64][1620]
    const float* mk = (const float*)d_in[1];   // [64][32400]
    const float* mv = (const float*)d_in[2];   // [1536][32400]
    float* out = (float*)d_out;                // [1536][1620]
    (void)in_sizes; (void)n_in; (void)out_size;

    k_asq<<<(MD + 255) / 256, 256>>>(mk);                                    // 1
    k_transpose<<<dim3((MD + 31) / 32, CHD / 32), dim3(32, 8)>>>(mv);        // 2
    k_mkt<<<dim3(MPAD / 32, CKD / 32), dim3(32, 8)>>>(mk);                   // 3

    cudaFuncSetAttribute(k_affA, cudaFuncAttributeMaxDynamicSharedMemorySize, SB_TOTAL);
    cudaFuncSetAttribute(k_affB, cudaFuncAttributeMaxDynamicSharedMemorySize, SB_TOTAL);
    k_affA<<<dim3(NQB, NCHUNK), 256, SB_TOTAL>>>(qk);                        // 4 (ncu slot)
    k_thresh<<<(QD + 255) / 256, 256>>>();                                   // 5
    k_affB<<<dim3(NQB, NCHUNK), 256, SB_TOTAL>>>(qk);                        // 6
    k_rescue<<<(QD + 7) / 8, 256>>>(qk);                                     // 7
    k_readout<<<dim3((QD + QT3 - 1) / QT3, CHD / 256), 256>>>(out);          // 8
}

// round 10
// speedup vs baseline: 15.2896x; 1.2295x over previous
#include <cuda_runtime.h>
#include <cuda_bf16.h>
#include <cuda_fp16.h>
#include <math.h>
#include <stdint.h>

// ---------------- problem constants ----------------
#define CKD 64
#define QD 1620          // H*W
#define MD 32400
#define TOPK 20
#define CHD 1536         // OD*CVD

// ---------------- filter tiling ----------------
#define QT 128           // q per block
#define MTILE 64         // m per iteration
#define NQB 13           // 13*128 = 1664 >= 1620
#define NCHUNK 22
#define CHUNKP 1536      // m per chunk
#define ITERS1 24        // CHUNKP / MTILE
#define MPAD (NCHUNK * CHUNKP)   // 33792
#define HCAP 512         // per-q hit capacity
#define NSTAGE 4
#define QT3 16

// ---------------- device scratch ----------------
__device__ __align__(16) float g_nasq[MPAD];                   // -0.125*||mk||^2; pad = -1e37
__device__ __align__(16) __nv_bfloat16 g_mkt[(size_t)MPAD * CKD];  // mk^T bf16 [m][c]
__device__ __align__(16) float g_mktf[(size_t)MD * CKD];       // mk^T fp32 (exact)
__device__ __align__(16) __half g_vth[(size_t)MD * CHD];       // mem_v^T fp16 [m][1536]
__device__ unsigned g_chunkmax[NQB * QT * NCHUNK];
__device__ float g_thresh[QD];
__device__ int   g_hcnt[QD];
__device__ int   g_hits[(size_t)QD * HCAP];
__device__ float g_wval[QD * TOPK];
__device__ int   g_widx[QD * TOPK];

// order-preserving float<->uint map (unsigned domain)
__device__ __forceinline__ unsigned encf(float v) {
    unsigned b = __float_as_uint(v);
    return (b & 0x80000000u) ? ~b : (b | 0x80000000u);
}
__device__ __forceinline__ float decf(unsigned u) {
    unsigned b = (u & 0x80000000u) ? (u & 0x7FFFFFFFu) : ~u;
    return __uint_as_float(b);
}

// ---------------- async copy helpers ----------------
#define CP_ASYNC16(dst, src) \
    asm volatile("cp.async.cg.shared.global [%0], [%1], 16;" :: "r"(dst), "l"(src))
#define CP_COMMIT() asm volatile("cp.async.commit_group;")
#define CP_WAIT2()  asm volatile("cp.async.wait_group 2;" ::: "memory")

// ---------------- mma helper ----------------
__device__ __forceinline__ void mma_bf16(float* c, const uint32_t* a,
                                         uint32_t b0, uint32_t b1) {
    asm volatile(
        "mma.sync.aligned.m16n8k16.row.col.f32.bf16.bf16.f32 "
        "{%0,%1,%2,%3}, {%4,%5,%6,%7}, {%8,%9}, {%0,%1,%2,%3};"
        : "+f"(c[0]), "+f"(c[1]), "+f"(c[2]), "+f"(c[3])
        : "r"(a[0]), "r"(a[1]), "r"(a[2]), "r"(a[3]), "r"(b0), "r"(b1));
}

// ---------------- K0: -0.125*||mk||^2 over padded range ----------------------
__global__ void k_asq(const float* __restrict__ mk) {
    int m = blockIdx.x * 256 + threadIdx.x;
    if (m >= MPAD) return;
    if (m >= MD) { g_nasq[m] = -1.0e37f; return; }
    float s = 0.f;
    #pragma unroll
    for (int c = 0; c < CKD; c++) {
        float v = mk[c * MD + m];
        s += v * v;
    }
    g_nasq[m] = -(s * 0.125f);
}

// ---------------- KT: mem_v transpose [1536][M] -> fp16 [M][1536] ------------
__global__ void k_transpose(const float* __restrict__ v) {
    __shared__ float tile[32][33];
    int m0 = blockIdx.x * 32, c0 = blockIdx.y * 32;
    int tx = threadIdx.x, ty = threadIdx.y;
    #pragma unroll
    for (int i = ty; i < 32; i += 8) {
        int m = m0 + tx;
        tile[i][tx] = (m < MD) ? v[(size_t)(c0 + i) * MD + m] : 0.f;
    }
    __syncthreads();
    #pragma unroll
    for (int i = ty; i < 32; i += 8) {
        int m = m0 + i;
        if (m < MD) g_vth[(size_t)m * CHD + c0 + tx] = __float2half(tile[tx][i]);
    }
}

// ---------------- KM: mk transpose -> bf16 g_mkt + fp32 g_mktf ---------------
__global__ void k_mkt(const float* __restrict__ mk) {
    __shared__ float tile[32][33];
    int m0 = blockIdx.x * 32, c0 = blockIdx.y * 32;
    int tx = threadIdx.x, ty = threadIdx.y;
    #pragma unroll
    for (int i = ty; i < 32; i += 8) {
        int m = m0 + tx;
        tile[i][tx] = (m < MD) ? mk[(size_t)(c0 + i) * MD + m] : 0.f;
    }
    __syncthreads();
    #pragma unroll
    for (int i = ty; i < 32; i += 8) {
        int m = m0 + i;
        float v = tile[tx][i];
        g_mkt[(size_t)m * CKD + c0 + tx] = __float2bfloat16(v);
        if (m < MD) g_mktf[(size_t)m * CKD + c0 + tx] = v;
    }
}

// ---------------- filter GEMM common smem layout (bytes) ----------------
#define SB_QKB   0                       // bf16 qk [128][68] = 17408
#define SB_B     17408                   // NSTAGE x (64 rows x 144B) = 36864
#define SB_NASQ  54272                   // NSTAGE x 256B = 1024
#define SB_RED   55296                   // 128 unsigned = 512
#define SB_TOTAL 55808

// async-stage B tile (64m x 64c bf16, row stride 144B) + nasq row
#define STAGE_B_ASYNC(s, mb) do { \
    const char* _gs = (const char*)g_mkt + (size_t)(mb) * (CKD * 2); \
    uint32_t _bb = sbase + SB_B + (s) * 9216; \
    _Pragma("unroll") \
    for (int _i = 0; _i < 2; _i++) { \
        int _idx = tid + _i * 256; \
        int _m = _idx >> 3, _c16 = _idx & 7; \
        CP_ASYNC16(_bb + _m * 144 + _c16 * 16, _gs + _m * 128 + _c16 * 16); \
    } \
    if (tid < 16) \
        CP_ASYNC16(sbase + SB_NASQ + (s) * 256 + tid * 16, \
                   (const char*)g_nasq + (size_t)(mb) * 4 + tid * 16); \
} while (0)

#define STAGE_QKB() do { \
    for (int t = tid; t < CKD * QT; t += 256) { \
        int c = t >> 7, j = t & 127; \
        int q = q0 + j; \
        float v = (q < QD) ? qk[c * QD + q] : 0.f; \
        qkb[j * 68 + c] = __float2bfloat16(v); \
    } \
} while (0)

#define LOAD_AFR() do { \
    _Pragma("unroll") \
    for (int Mt = 0; Mt < 2; Mt++) { \
        _Pragma("unroll") \
        for (int ks = 0; ks < 4; ks++) { \
            int qr = qw * 32 + Mt * 16 + r8; \
            int cc = ks * 16 + 2 * t4; \
            afr[Mt][ks][0] = *(const uint32_t*)&qkb[qr * 68 + cc]; \
            afr[Mt][ks][1] = *(const uint32_t*)&qkb[(qr + 8) * 68 + cc]; \
            afr[Mt][ks][2] = *(const uint32_t*)&qkb[qr * 68 + cc + 8]; \
            afr[Mt][ks][3] = *(const uint32_t*)&qkb[(qr + 8) * 68 + cc + 8]; \
        } \
    } \
} while (0)

#define DO_MMA(s) do { \
    const uint32_t* Bb = (const uint32_t*)(sm + SB_B + (s) * 9216); \
    _Pragma("unroll") \
    for (int ks = 0; ks < 4; ks++) { \
        _Pragma("unroll") \
        for (int Nt = 0; Nt < 4; Nt++) { \
            int nl = mw * 32 + Nt * 8 + r8; \
            uint32_t b0 = Bb[nl * 36 + ks * 8 + t4]; \
            uint32_t b1 = Bb[nl * 36 + ks * 8 + t4 + 4]; \
            mma_bf16(acc[0][Nt], afr[0][ks], b0, b1); \
            mma_bf16(acc[1][Nt], afr[1][ks], b0, b1); \
        } \
    } \
} while (0)

// ---------------- K1a: filter GEMM -> per-(q,chunk) max ----------------------
__global__ void __launch_bounds__(256, 2) k_affA(const float* __restrict__ qk) {
    extern __shared__ char sm[];
    __nv_bfloat16* qkb = (__nv_bfloat16*)(sm + SB_QKB);
    unsigned* red = (unsigned*)(sm + SB_RED);
    const uint32_t sbase = (uint32_t)__cvta_generic_to_shared(sm);

    const int tid = threadIdx.x, lane = tid & 31, wid = tid >> 5;
    const int qw = wid >> 1, mw = wid & 1;
    const int r8 = lane >> 2, t4 = lane & 3;
    const int q0 = blockIdx.x * QT;
    const int chunk = blockIdx.y;
    const int mc0 = chunk * CHUNKP;

    STAGE_QKB();
    if (tid < QT) red[tid] = 0u;

    // preload 3 stages
    #pragma unroll
    for (int s = 0; s < NSTAGE - 1; s++) {
        STAGE_B_ASYNC(s, mc0 + s * MTILE);
        CP_COMMIT();
    }
    __syncthreads();

    uint32_t afr[2][4][4];
    LOAD_AFR();

    float rmax[4] = {-3.0e38f, -3.0e38f, -3.0e38f, -3.0e38f};

    for (int it = 0; it < ITERS1; it++) {
        const int s = it & (NSTAGE - 1);
        CP_WAIT2();
        __syncthreads();

        float acc[2][4][4];
        #pragma unroll
        for (int i = 0; i < 2; i++)
            #pragma unroll
            for (int j = 0; j < 4; j++)
                #pragma unroll
                for (int e = 0; e < 4; e++) acc[i][j][e] = 0.f;

        DO_MMA(s);

        // prefetch 3 ahead (uniform group accounting: always commit one group)
        if (it + NSTAGE - 1 < ITERS1) {
            STAGE_B_ASYNC((it + NSTAGE - 1) & (NSTAGE - 1), mc0 + (it + NSTAGE - 1) * MTILE);
        }
        CP_COMMIT();

        // epilogue: running max of 0.25*dot + nasq
        const float* nq = (const float*)(sm + SB_NASQ + s * 256);
        #pragma unroll
        for (int Mt = 0; Mt < 2; Mt++) {
            #pragma unroll
            for (int Nt = 0; Nt < 4; Nt++) {
                int ml = mw * 32 + Nt * 8 + 2 * t4;
                float2 nn = *(const float2*)&nq[ml];
                float a0 = fmaxf(0.25f * acc[Mt][Nt][0] + nn.x, 0.25f * acc[Mt][Nt][1] + nn.y);
                float a1 = fmaxf(0.25f * acc[Mt][Nt][2] + nn.x, 0.25f * acc[Mt][Nt][3] + nn.y);
                rmax[2 * Mt + 0] = fmaxf(rmax[2 * Mt + 0], a0);
                rmax[2 * Mt + 1] = fmaxf(rmax[2 * Mt + 1], a1);
            }
        }
    }

    // reduce across t4 lanes, then across mw warps via smem atomicMax (unsigned)
    #pragma unroll
    for (int i = 0; i < 4; i++) {
        #pragma unroll
        for (int s2 = 1; s2 <= 2; s2 <<= 1) {
            float o = __shfl_xor_sync(0xffffffffu, rmax[i], s2);
            rmax[i] = fmaxf(rmax[i], o);
        }
    }
    if (t4 == 0) {
        #pragma unroll
        for (int i = 0; i < 4; i++) {
            int row = qw * 32 + (i >> 1) * 16 + r8 + (i & 1) * 8;
            atomicMax(&red[row], encf(rmax[i]));
        }
    }
    __syncthreads();
    if (tid < QT) g_chunkmax[(q0 + tid) * NCHUNK + chunk] = red[tid];
}

// ---------------- K2a: threshold = 20th-largest chunk max - margin ----------
__global__ void k_thresh() {
    int q = blockIdx.x * 256 + threadIdx.x;
    if (q >= QD) return;
    unsigned s1 = 0xFFFFFFFFu, s2 = 0xFFFFFFFFu, s3 = 0xFFFFFFFFu;
    #pragma unroll
    for (int c = 0; c < NCHUNK; c++) {
        unsigned u = g_chunkmax[q * NCHUNK + c];
        if (u < s1)      { s3 = s2; s2 = s1; s1 = u; }
        else if (u < s2) { s3 = s2; s2 = u; }
        else if (u < s3) { s3 = u; }
    }
    g_thresh[q] = decf(s3) - 0.0625f;
    g_hcnt[q] = 0;
}

// ---------------- K1b: filter GEMM -> collect hits >= threshold --------------
__global__ void __launch_bounds__(256, 2) k_affB(const float* __restrict__ qk) {
    extern __shared__ char sm[];
    __nv_bfloat16* qkb = (__nv_bfloat16*)(sm + SB_QKB);
    const uint32_t sbase = (uint32_t)__cvta_generic_to_shared(sm);

    const int tid = threadIdx.x, lane = tid & 31, wid = tid >> 5;
    const int qw = wid >> 1, mw = wid & 1;
    const int r8 = lane >> 2, t4 = lane & 3;
    const int q0 = blockIdx.x * QT;
    const int chunk = blockIdx.y;
    const int mc0 = chunk * CHUNKP;

    STAGE_QKB();

    #pragma unroll
    for (int s = 0; s < NSTAGE - 1; s++) {
        STAGE_B_ASYNC(s, mc0 + s * MTILE);
        CP_COMMIT();
    }
    __syncthreads();

    uint32_t afr[2][4][4];
    LOAD_AFR();

    float T[4];
    int qg[4];
    #pragma unroll
    for (int i = 0; i < 4; i++) {
        int row = qw * 32 + (i >> 1) * 16 + r8 + (i & 1) * 8;
        qg[i] = q0 + row;
        T[i] = (qg[i] < QD) ? g_thresh[qg[i]] : 3.4e38f;
    }

    for (int it = 0; it < ITERS1; it++) {
        const int s = it & (NSTAGE - 1);
        const int m_base = mc0 + it * MTILE;
        CP_WAIT2();
        __syncthreads();

        float acc[2][4][4];
        #pragma unroll
        for (int i = 0; i < 2; i++)
            #pragma unroll
            for (int j = 0; j < 4; j++)
                #pragma unroll
                for (int e = 0; e < 4; e++) acc[i][j][e] = 0.f;

        DO_MMA(s);

        if (it + NSTAGE - 1 < ITERS1) {
            STAGE_B_ASYNC((it + NSTAGE - 1) & (NSTAGE - 1), mc0 + (it + NSTAGE - 1) * MTILE);
        }
        CP_COMMIT();

        const float* nq = (const float*)(sm + SB_NASQ + s * 256);
        #pragma unroll
        for (int Mt = 0; Mt < 2; Mt++) {
            #pragma unroll
            for (int Nt = 0; Nt < 4; Nt++) {
                int ml = mw * 32 + Nt * 8 + 2 * t4;
                float2 nn = *(const float2*)&nq[ml];
                float v00 = 0.25f * acc[Mt][Nt][0] + nn.x;
                float v01 = 0.25f * acc[Mt][Nt][1] + nn.y;
                float v10 = 0.25f * acc[Mt][Nt][2] + nn.x;
                float v11 = 0.25f * acc[Mt][Nt][3] + nn.y;
                int i0 = 2 * Mt, i1 = 2 * Mt + 1;
                if (v00 >= T[i0]) {
                    int p = atomicAdd(&g_hcnt[qg[i0]], 1);
                    if (p < HCAP) g_hits[(size_t)qg[i0] * HCAP + p] = m_base + ml;
                }
                if (v01 >= T[i0]) {
                    int p = atomicAdd(&g_hcnt[qg[i0]], 1);
                    if (p < HCAP) g_hits[(size_t)qg[i0] * HCAP + p] = m_base + ml + 1;
                }
                if (v10 >= T[i1]) {
                    int p = atomicAdd(&g_hcnt[qg[i1]], 1);
                    if (p < HCAP) g_hits[(size_t)qg[i1] * HCAP + p] = m_base + ml;
                }
                if (v11 >= T[i1]) {
                    int p = atomicAdd(&g_hcnt[qg[i1]], 1);
                    if (p < HCAP) g_hits[(size_t)qg[i1] * HCAP + p] = m_base + ml + 1;
                }
            }
        }
    }
}

// ---------------- K2: exact fp32 eval of hits + top-20 + softmax -------------
__global__ void k_rescue(const float* __restrict__ qk) {
    __shared__ int   pool[8][HCAP];
    __shared__ float pval[8][HCAP];
    __shared__ float qcol[8][CKD];

    int w = threadIdx.x >> 5, lane = threadIdx.x & 31;
    int q = blockIdx.x * 8 + w;
    if (q >= QD) return;

    qcol[w][lane] = qk[lane * QD + q];
    qcol[w][lane + 32] = qk[(lane + 32) * QD + q];
    int cnt = g_hcnt[q];
    if (cnt > HCAP) cnt = HCAP;
    const int* hp = g_hits + (size_t)q * HCAP;
    for (int i = lane; i < cnt; i += 32) pool[w][i] = hp[i];
    __syncwarp();

    for (int i = lane; i < cnt; i += 32) {
        int m = pool[w][i];
        const float4* kr = (const float4*)(g_mktf + (size_t)m * CKD);
        float dot = 0.f;
        #pragma unroll
        for (int c4 = 0; c4 < 16; c4++) {
            float4 kv = kr[c4];
            dot += kv.x * qcol[w][c4 * 4 + 0] + kv.y * qcol[w][c4 * 4 + 1]
                 + kv.z * qcol[w][c4 * 4 + 2] + kv.w * qcol[w][c4 * 4 + 3];
        }
        pval[w][i] = 0.25f * dot + g_nasq[m];
    }
    __syncwarp();

    uint64_t bestk = 0;
    for (int i = lane; i < cnt; i += 32) {
        uint64_t k = ((uint64_t)encf(pval[w][i]) << 32) | (uint32_t)(0xFFFFFFFFu - (uint32_t)pool[w][i]);
        if (k > bestk) bestk = k;
    }

    float vmax = 0.f, sum = 0.f;
    float myv = 0.f;
    int   myi = 0;
    for (int r = 0; r < TOPK; r++) {
        uint64_t k = bestk;
        #pragma unroll
        for (int s = 16; s > 0; s >>= 1) {
            uint64_t o = __shfl_xor_sync(0xffffffffu, k, s);
            if (o > k) k = o;
        }
        float kv = decf((unsigned)(k >> 32));
        if (r == 0) vmax = kv;
        sum += expf(kv - vmax);
        if (lane == r) { myv = kv; myi = (int)(0xFFFFFFFFu - (uint32_t)k); }
        if (k == bestk && k != 0) {
            uint64_t nb = 0;
            for (int i = lane; i < cnt; i += 32) {
                uint64_t kk = ((uint64_t)encf(pval[w][i]) << 32) | (uint32_t)(0xFFFFFFFFu - (uint32_t)pool[w][i]);
                if (kk == k) pval[w][i] = -3.4e38f;
                else if (kk > nb && kk < k) nb = kk;
            }
            bestk = nb;
        }
    }
    if (lane < TOPK) {
        g_wval[q * TOPK + lane] = expf(myv - vmax) / sum;
        g_widx[q * TOPK + lane] = myi;
    }
}

// ---------------- K3: sparse readout (fp16 v, half2 loads) -------------------
// grid (ceil(QD/16), CHD/512), block 256; thread owns ch-pair ch2.
__global__ void k_readout(float* __restrict__ out) {
    __shared__ float sw[QT3 * TOPK];
    __shared__ int   si[QT3 * TOPK];
    int q0 = blockIdx.x * QT3;
    int ch2 = blockIdx.y * 256 + threadIdx.x;   // half2 index (768 total)
    for (int t = threadIdx.x; t < QT3 * TOPK; t += 256) {
        int q = q0 + t / TOPK;
        if (q < QD) {
            sw[t] = g_wval[q * TOPK + (t % TOPK)];
            si[t] = g_widx[q * TOPK + (t % TOPK)];
        } else { sw[t] = 0.f; si[t] = 0; }
    }
    __syncthreads();

    const __half2* vt2 = (const __half2*)g_vth;
    float2 acc[QT3];
    #pragma unroll
    for (int j = 0; j < QT3; j++) acc[j] = make_float2(0.f, 0.f);

    #pragma unroll
    for (int k = 0; k < TOPK; k++) {
        #pragma unroll
        for (int j = 0; j < QT3; j++) {
            float w = sw[j * TOPK + k];
            int   m = si[j * TOPK + k];
            float2 f = __half22float2(vt2[(size_t)m * (CHD / 2) + ch2]);
            acc[j].x += w * f.x;
            acc[j].y += w * f.y;
        }
    }

    int ch0 = ch2 * 2;
    if (q0 + QT3 <= QD) {
        float4* o0 = (float4*)(out + (size_t)ch0 * QD + q0);
        float4* o1 = (float4*)(out + (size_t)(ch0 + 1) * QD + q0);
        #pragma unroll
        for (int jj = 0; jj < QT3 / 4; jj++) {
            o0[jj] = make_float4(acc[jj*4].x, acc[jj*4+1].x, acc[jj*4+2].x, acc[jj*4+3].x);
            o1[jj] = make_float4(acc[jj*4].y, acc[jj*4+1].y, acc[jj*4+2].y, acc[jj*4+3].y);
        }
    } else {
        #pragma unroll
        for (int j = 0; j < QT3; j++) {
            int q = q0 + j;
            if (q < QD) {
                out[(size_t)ch0 * QD + q] = acc[j].x;
                out[(size_t)(ch0 + 1) * QD + q] = acc[j].y;
            }
        }
    }
}

// ---------------- launch ----------------
extern "C" void kernel_launch(void* const* d_in, const int* in_sizes, int n_in,
                              void* d_out, int out_size) {
    const float* qk = (const float*)d_in[0];   // [64][1620]
    const float* mk = (const float*)d_in[1];   // [64][32400]
    const float* mv = (const float*)d_in[2];   // [1536][32400]
    float* out = (float*)d_out;                // [1536][1620]
    (void)in_sizes; (void)n_in; (void)out_size;

    k_asq<<<(MPAD + 255) / 256, 256>>>(mk);                                  // 1
    k_transpose<<<dim3((MD + 31) / 32, CHD / 32), dim3(32, 8)>>>(mv);        // 2
    k_mkt<<<dim3(MPAD / 32, CKD / 32), dim3(32, 8)>>>(mk);                   // 3

    cudaFuncSetAttribute(k_affA, cudaFuncAttributeMaxDynamicSharedMemorySize, SB_TOTAL);
    cudaFuncSetAttribute(k_affB, cudaFuncAttributeMaxDynamicSharedMemorySize, SB_TOTAL);
    k_affA<<<dim3(NQB, NCHUNK), 256, SB_TOTAL>>>(qk);                        // 4 (ncu slot)
    k_thresh<<<(QD + 255) / 256, 256>>>();                                   // 5
    k_affB<<<dim3(NQB, NCHUNK), 256, SB_TOTAL>>>(qk);                        // 6
    k_rescue<<<(QD + 7) / 8, 256>>>(qk);                                     // 7
    k_readout<<<dim3((QD + QT3 - 1) / QT3, CHD / 512), 256>>>(out);          // 8
}